// round 9
// baseline (speedup 1.0000x reference)
#include <cuda_runtime.h>
#include <cuda_bf16.h>

// Problem constants
#define NS 5
#define ND 64
#define NV 1024
#define NH 961
#define HPITCH 1092   // 63 zeros | 961 taps | 68 zeros (16B-aligned rows)
#define BPITCH 1088
#define MAXB 4096

// Precomputed once per launch:
__device__ float g_hp[NS][HPITCH];   // zero-padded taps
__device__ float g_hb[NS][BPITCH];   // g_hb[i] = g_hp[i+1] (sp_kernel conv)
__device__ float g_sp[NS][NV];       // sp = conv_net(symbols)
// Split-bf16 operands for the conv GEMM:
//   GT[s][o][d] = hp[s][d + 1023 - o]  (B operand, K-contiguous rows)
__device__ __align__(16) __nv_bfloat16 g_GThi[NS][NV][ND];
__device__ __align__(16) __nv_bfloat16 g_GTlo[NS][NV][ND];
__device__ __align__(16) __nv_bfloat16 g_Xhi[MAXB * NS * ND];
__device__ __align__(16) __nv_bfloat16 g_Xlo[MAXB * NS * ND];
// Conv output staging (fp32)
__device__ float g_Y[(size_t)MAXB * NS * NV];

__device__ __forceinline__ float silu_f(float y) {
    return y * (1.0f / (1.0f + __expf(-y)));
}

__device__ __forceinline__ float warp_sum(float v) {
#pragma unroll
    for (int o = 16; o; o >>= 1) v += __shfl_xor_sync(0xffffffffu, v, o);
    return v;
}

__device__ __forceinline__ void ffma2(unsigned long long& acc,
                                      unsigned long long x,
                                      unsigned long long g) {
    asm("fma.rn.f32x2 %0, %1, %2, %0;" : "+l"(acc) : "l"(x), "l"(g));
}
__device__ __forceinline__ float u64lo(unsigned long long u) {
    return __uint_as_float((unsigned)u);
}
__device__ __forceinline__ float u64hi(unsigned long long u) {
    return __uint_as_float((unsigned)(u >> 32));
}

// m16n8k16 row.col bf16 MMA, fp32 accumulate (D == C).
// A frag (lane g=l>>2, t=l&3): a0=A[g][2t,2t+1] a1=A[g+8][2t,2t+1]
//                              a2=A[g][2t+8,2t+9] a3=A[g+8][2t+8,2t+9]
// B frag: b0=B[2t,2t+1][g]  b1=B[2t+8,2t+9][g]   (B is K x N)
// C frag: c0=C[g][2t] c1=C[g][2t+1] c2=C[g+8][2t] c3=C[g+8][2t+1]
__device__ __forceinline__ void mma16816(float* c, const unsigned* a,
                                         const unsigned* b) {
    asm volatile(
        "mma.sync.aligned.m16n8k16.row.col.f32.bf16.bf16.f32 "
        "{%0,%1,%2,%3}, {%4,%5,%6,%7}, {%8,%9}, {%0,%1,%2,%3};\n"
        : "+f"(c[0]), "+f"(c[1]), "+f"(c[2]), "+f"(c[3])
        : "r"(a[0]), "r"(a[1]), "r"(a[2]), "r"(a[3]), "r"(b[0]), "r"(b[1]));
}

// ---- fully packed scalar conv (sp_kernel only; exact fp32) ----
__device__ __forceinline__ void conv4p(const float* __restrict__ gA,
                                       const float* __restrict__ gB,
                                       const float* __restrict__ xs,
                                       float a[4]) {
    const ulonglong2* a2v = (const ulonglong2*)gA;
    const ulonglong2* b2v = (const ulonglong2*)gB;
    const ulonglong2* x2v = (const ulonglong2*)xs;
    unsigned long long A3 = 0ull, A2 = 0ull, A1 = 0ull, A0 = 0ull;
    ulonglong2 GA = a2v[0];
    ulonglong2 GB = b2v[0];
#pragma unroll
    for (int m = 0; m < 16; m++) {
        const ulonglong2 GAn = a2v[m + 1];
        const ulonglong2 GBn = b2v[m + 1];
        const ulonglong2 X = x2v[m];
        ffma2(A3, X.x, GA.x);
        ffma2(A1, X.x, GA.y);
        ffma2(A2, X.x, GB.x);
        ffma2(A0, X.x, GB.y);
        ffma2(A3, X.y, GA.y);
        ffma2(A1, X.y, GAn.x);
        ffma2(A2, X.y, GB.y);
        ffma2(A0, X.y, GBn.x);
        GA = GAn;
        GB = GBn;
    }
    a[3] = u64lo(A3) + u64hi(A3);
    a[2] = u64lo(A2) + u64hi(A2);
    a[1] = u64lo(A1) + u64hi(A1);
    a[0] = u64lo(A0) + u64hi(A0);
}

// --------------------------------------------------------------------------
// Kernel 1: pads h (g_hp/g_hb), builds split-bf16 GT, computes sp.
// --------------------------------------------------------------------------
__global__ __launch_bounds__(256) void sp_kernel(
    const float* __restrict__ h, const float* __restrict__ symbols,
    const float* __restrict__ gamma, const float* __restrict__ beta) {
    __shared__ __align__(16) float hpA[HPITCH];
    __shared__ __align__(16) float hpB[BPITCH];
    __shared__ __align__(16) float xs[ND];
    __shared__ float wsum[8], wsq[8], mu_rs[2];
    const int s = blockIdx.x;
    const int t = threadIdx.x;
    const int warp = t >> 5, lane = t & 31;

    for (int i = t; i < HPITCH; i += 256) {
        const float v = (i >= 63 && i < 63 + NH) ? h[s * NH + (i - 63)] : 0.f;
        hpA[i] = v;
        g_hp[s][i] = v;
    }
    for (int i = t; i < BPITCH; i += 256) {
        const int j = i + 1;
        const float v = (j >= 63 && j < 63 + NH) ? h[s * NH + (j - 63)] : 0.f;
        hpB[i] = v;
        g_hb[s][i] = v;
    }
    if (t < ND) xs[t] = symbols[s * ND + t];
    __syncthreads();

    // build GT split-bf16: GT[o][d] = hp[d + 1023 - o]
    for (int idx = t; idx < NV * ND; idx += 256) {
        const int o = idx >> 6, d = idx & 63;
        const float v = hpA[d + 1023 - o];
        const __nv_bfloat16 hi = __float2bfloat16(v);
        g_GThi[s][o][d] = hi;
        g_GTlo[s][o][d] = __float2bfloat16(v - __bfloat162float(hi));
    }

    const int o0 = 4 * t;
    float a[4];
    conv4p(hpA + (1020 - o0), hpB + (1020 - o0), xs, a);

    float sm = 0.f, sq = 0.f;
#pragma unroll
    for (int k = 0; k < 4; k++) {
        a[k] = silu_f(a[k]);
        sm += a[k];
        sq += a[k] * a[k];
    }
    sm = warp_sum(sm);
    sq = warp_sum(sq);
    if (lane == 0) { wsum[warp] = sm; wsq[warp] = sq; }
    __syncthreads();
    if (t == 0) {
        float s1 = 0.f, s2 = 0.f;
#pragma unroll
        for (int w = 0; w < 8; w++) { s1 += wsum[w]; s2 += wsq[w]; }
        const float mu = s1 * (1.f / NV);
        mu_rs[0] = mu;
        mu_rs[1] = rsqrtf(s2 * (1.f / NV) - mu * mu + 1e-3f);
    }
    __syncthreads();
    const float mu = mu_rs[0], rstd = mu_rs[1];
#pragma unroll
    for (int k = 0; k < 4; k++) {
        const int o = o0 + k;
        g_sp[s][o] = (a[k] - mu) * rstd * gamma[o] + beta[o];
    }
}

// --------------------------------------------------------------------------
// Kernel 2: split x (fp32 -> bf16 hi + bf16 lo)
// --------------------------------------------------------------------------
__global__ __launch_bounds__(256) void xprep_kernel(
    const float* __restrict__ values, int n) {
    const int i = (blockIdx.x * 256 + threadIdx.x) * 4;
    if (i < n) {
        const float4 v = *(const float4*)(values + i);
        __nv_bfloat16 h0 = __float2bfloat16(v.x);
        __nv_bfloat16 h1 = __float2bfloat16(v.y);
        __nv_bfloat16 h2 = __float2bfloat16(v.z);
        __nv_bfloat16 h3 = __float2bfloat16(v.w);
        __nv_bfloat162* ph = (__nv_bfloat162*)(&g_Xhi[i]);
        ph[0] = __nv_bfloat162(h0, h1);
        ph[1] = __nv_bfloat162(h2, h3);
        __nv_bfloat162* pl = (__nv_bfloat162*)(&g_Xlo[i]);
        pl[0] = __nv_bfloat162(__float2bfloat16(v.x - __bfloat162float(h0)),
                               __float2bfloat16(v.y - __bfloat162float(h1)));
        pl[1] = __nv_bfloat162(__float2bfloat16(v.z - __bfloat162float(h2)),
                               __float2bfloat16(v.w - __bfloat162float(h3)));
    }
}

// --------------------------------------------------------------------------
// Kernel 3: conv GEMM. Y[b][s][o] = sum_d X[b][s][d] * GT[s][o][d].
// Tile: M=128 (batch rows) x N=128 (o) x K=64, 3 split-bf16 terms.
// 8 warps = 4(m) x 2(n); warp tile 32x64. B (GT) staged in padded SMEM.
// --------------------------------------------------------------------------
__global__ __launch_bounds__(256) void gemm_kernel(int B) {
    __shared__ __align__(16) __nv_bfloat16 sBhi[128][72];  // +16B pad per row
    __shared__ __align__(16) __nv_bfloat16 sBlo[128][72];

    const int s = blockIdx.z;
    const int n0 = blockIdx.y * 128;
    const int bm0 = blockIdx.x * 128;
    const int t = threadIdx.x;

    {   // stage GT tile rows n0..n0+127 (64 bf16 each) for hi and lo
        const int row = t >> 1, half = t & 1;
        const int base = (((n0 + row) << 6) + (half << 5)) >> 2;  // uint2 idx
        const uint2* srchi = (const uint2*)(&g_GThi[s][0][0]);
        const uint2* srclo = (const uint2*)(&g_GTlo[s][0][0]);
        uint2* dsthi = (uint2*)(&sBhi[row][half * 32]);
        uint2* dstlo = (uint2*)(&sBlo[row][half * 32]);
#pragma unroll
        for (int j = 0; j < 8; j++) {
            dsthi[j] = srchi[base + j];
            dstlo[j] = srclo[base + j];
        }
    }
    __syncthreads();

    const int warp = t >> 5, lane = t & 31;
    const int wm = warp & 3, wn = warp >> 2;
    const int g = lane >> 2, t4 = lane & 3;
    const int rbase = bm0 + wm * 32;

    float acc[2][8][4];
#pragma unroll
    for (int mi = 0; mi < 2; mi++)
#pragma unroll
        for (int j = 0; j < 8; j++)
#pragma unroll
            for (int c = 0; c < 4; c++) acc[mi][j][c] = 0.f;

    const unsigned* ph = (const unsigned*)g_Xhi;
    const unsigned* pl = (const unsigned*)g_Xlo;

#pragma unroll
    for (int ks = 0; ks < 4; ks++) {
        const int k0 = ks * 16;
        unsigned ahi[2][4], alo[2][4];
#pragma unroll
        for (int mi = 0; mi < 2; mi++) {
            const int r0 = min(rbase + mi * 16 + g, B - 1);
            const int r8 = min(rbase + mi * 16 + g + 8, B - 1);
            const int i0 = ((r0 * NS + s) * ND + k0 + 2 * t4) >> 1;
            const int i8 = ((r8 * NS + s) * ND + k0 + 2 * t4) >> 1;
            ahi[mi][0] = ph[i0];     ahi[mi][1] = ph[i8];
            ahi[mi][2] = ph[i0 + 4]; ahi[mi][3] = ph[i8 + 4];
            alo[mi][0] = pl[i0];     alo[mi][1] = pl[i8];
            alo[mi][2] = pl[i0 + 4]; alo[mi][3] = pl[i8 + 4];
        }
#pragma unroll
        for (int j = 0; j < 8; j++) {
            const int nl = wn * 64 + j * 8 + g;
            unsigned bh[2], bl[2];
            bh[0] = *(const unsigned*)&sBhi[nl][k0 + 2 * t4];
            bh[1] = *(const unsigned*)&sBhi[nl][k0 + 2 * t4 + 8];
            bl[0] = *(const unsigned*)&sBlo[nl][k0 + 2 * t4];
            bl[1] = *(const unsigned*)&sBlo[nl][k0 + 2 * t4 + 8];
#pragma unroll
            for (int mi = 0; mi < 2; mi++) {
                mma16816(acc[mi][j], ahi[mi], bh);
                mma16816(acc[mi][j], ahi[mi], bl);
                mma16816(acc[mi][j], alo[mi], bh);
            }
        }
    }

    // store Y
#pragma unroll
    for (int mi = 0; mi < 2; mi++) {
        const int r0 = rbase + mi * 16 + g;
#pragma unroll
        for (int j = 0; j < 8; j++) {
            const int col = n0 + wn * 64 + j * 8 + 2 * t4;
            if (r0 < B)
                *(float2*)(g_Y + ((size_t)r0 * NS + s) * NV + col) =
                    make_float2(acc[mi][j][0], acc[mi][j][1]);
            if (r0 + 8 < B)
                *(float2*)(g_Y + ((size_t)(r0 + 8) * NS + s) * NV + col) =
                    make_float2(acc[mi][j][2], acc[mi][j][3]);
        }
    }
}

// --------------------------------------------------------------------------
// Kernel 4: epilogue. One CTA per batch: silu+LN stats+LN, sign-scores,
// softmax(5), einsum, silu, store. Y row columns 4t..4t+3 live in registers.
// --------------------------------------------------------------------------
__global__ __launch_bounds__(256, 4) void epi_kernel(
    const float* __restrict__ gamma, const float* __restrict__ beta,
    float* __restrict__ out) {
    __shared__ float wsum[NS][8], wsq[NS][8];
    __shared__ float mu_s[NS], rs_s[NS];
    __shared__ int   spart[25][8];
    __shared__ float prob[NS][NS];

    const int b = blockIdx.x;
    const int t = threadIdx.x;
    const int warp = t >> 5, lane = t & 31;

    // load Y columns, apply silu, accumulate LN stats
    float4 VPX[NS];
#pragma unroll
    for (int i = 0; i < NS; i++) {
        float4 v = ((const float4*)(g_Y + ((size_t)b * NS + i) * NV))[t];
        v.x = silu_f(v.x); v.y = silu_f(v.y);
        v.z = silu_f(v.z); v.w = silu_f(v.w);
        VPX[i] = v;
        float sm = v.x + v.y + v.z + v.w;
        float sq = v.x * v.x + v.y * v.y + v.z * v.z + v.w * v.w;
        sm = warp_sum(sm);
        sq = warp_sum(sq);
        if (lane == 0) { wsum[i][warp] = sm; wsq[i][warp] = sq; }
    }
    __syncthreads();
    if (t < NS) {
        float s1 = 0.f, s2 = 0.f;
#pragma unroll
        for (int w = 0; w < 8; w++) { s1 += wsum[t][w]; s2 += wsq[t][w]; }
        const float mu = s1 * (1.f / NV);
        mu_s[t] = mu;
        rs_s[t] = rsqrtf(s2 * (1.f / NV) - mu * mu + 1e-3f);
    }
    __syncthreads();

    // layernorm in registers
    const float4 gm4 = ((const float4*)gamma)[t];
    const float4 bt4 = ((const float4*)beta)[t];
#pragma unroll
    for (int i = 0; i < NS; i++) {
        const float mu = mu_s[i], rs = rs_s[i];
        VPX[i].x = (VPX[i].x - mu) * rs * gm4.x + bt4.x;
        VPX[i].y = (VPX[i].y - mu) * rs * gm4.y + bt4.y;
        VPX[i].z = (VPX[i].z - mu) * rs * gm4.z + bt4.z;
        VPX[i].w = (VPX[i].w - mu) * rs * gm4.w + bt4.w;
    }

    float4 SP[NS];
#pragma unroll
    for (int j = 0; j < NS; j++) SP[j] = ((const float4*)(&g_sp[j][0]))[t];

    // scores: sign(v)*sign(v+sp) = 1 - 2*(signbit xor); count flips
#pragma unroll
    for (int j = 0; j < NS; j++) {
        const float spv[4] = {SP[j].x, SP[j].y, SP[j].z, SP[j].w};
#pragma unroll
        for (int i = 0; i < NS; i++) {
            const float vv[4] = {VPX[i].x, VPX[i].y, VPX[i].z, VPX[i].w};
            int a = 0;
#pragma unroll
            for (int k = 0; k < 4; k++) {
                const float c = vv[k] + spv[k];
                a += (int)((__float_as_uint(vv[k]) ^ __float_as_uint(c)) >> 31);
            }
            const int v = __reduce_add_sync(0xffffffffu, a);
            if (lane == 0) spart[j * NS + i][warp] = v;
        }
    }
    __syncthreads();
    if (t < 25) {
        int sm = 0;
#pragma unroll
        for (int w = 0; w < 8; w++) sm += spart[t][w];
        ((float*)&spart[t][0])[0] = (float)(NV - 2 * sm) * (1.f / NV);
    }
    __syncthreads();
    if (t < NS) {
        float sc[NS], m = -1e30f;
#pragma unroll
        for (int i = 0; i < NS; i++) {
            sc[i] = ((float*)&spart[t * NS + i][0])[0];
            m = fmaxf(m, sc[i]);
        }
        float ssum = 0.f;
#pragma unroll
        for (int i = 0; i < NS; i++) { sc[i] = __expf(sc[i] - m); ssum += sc[i]; }
        const float inv = 1.f / ssum;
#pragma unroll
        for (int i = 0; i < NS; i++) prob[t][i] = sc[i] * inv;
    }
    __syncthreads();

    float4* out4 = (float4*)(out + (size_t)b * (NS * NV));
#pragma unroll
    for (int j = 0; j < NS; j++) {
        const float p0 = prob[j][0], p1 = prob[j][1], p2 = prob[j][2],
                    p3 = prob[j][3], p4 = prob[j][4];
        const float spv[4] = {SP[j].x, SP[j].y, SP[j].z, SP[j].w};
        float r[4];
#pragma unroll
        for (int k = 0; k < 4; k++) {
            const float v0 = ((const float*)&VPX[0])[k];
            const float v1 = ((const float*)&VPX[1])[k];
            const float v2 = ((const float*)&VPX[2])[k];
            const float v3 = ((const float*)&VPX[3])[k];
            const float v4 = ((const float*)&VPX[4])[k];
            const float atv = p0 * v0 + p1 * v1 + p2 * v2 + p3 * v3 + p4 * v4;
            r[k] = silu_f(atv * spv[k]);
        }
        float4 w4;
        w4.x = r[0]; w4.y = r[1]; w4.z = r[2]; w4.w = r[3];
        out4[j * 256 + t] = w4;
    }
}

extern "C" void kernel_launch(void* const* d_in, const int* in_sizes, int n_in,
                              void* d_out, int out_size) {
    const float* values  = (const float*)d_in[0];
    const float* h       = (const float*)d_in[1];
    const float* symbols = (const float*)d_in[2];
    const float* gamma   = (const float*)d_in[3];
    const float* beta    = (const float*)d_in[4];
    float* out = (float*)d_out;

    const int B = in_sizes[0] / (NS * ND);
    const int nx = B * NS * ND;

    sp_kernel<<<NS, 256>>>(h, symbols, gamma, beta);
    xprep_kernel<<<(nx / 4 + 255) / 256, 256>>>(values, nx);
    dim3 ggrid((B + 127) / 128, NV / 128, NS);
    gemm_kernel<<<ggrid, 256>>>(B);
    epi_kernel<<<B, 256>>>(gamma, beta, out);
}